// round 4
// baseline (speedup 1.0000x reference)
#include <cuda_runtime.h>
#include <cstdint>
#include <math.h>

// Problem constants (fixed shapes)
#define N_BATCH 64
#define DIM     512   // d (contraction for QK)
#define CQ      512   // c (query positions)
#define TT      1024  // t = h*w
#define WW      128   // w
#define SCALE   0.04419417382415922f  // 512^-0.5

// Scratch (device globals: allowed, no cudaMalloc)
static __device__ float g_logits[(size_t)N_BATCH * CQ * TT];   // 128 MB
static __device__ float g_qt[(size_t)N_BATCH * CQ * DIM];      // 64 MB  Q^T [n][c][d] (scaled, tf32-rounded)
static __device__ float g_kt[(size_t)N_BATCH * TT * DIM];      // 128 MB K^T [n][t][d] -> reused for V_tf32 after GEMM1

// ---------------------------------------------------------------------------
// helpers
// ---------------------------------------------------------------------------
__device__ __forceinline__ uint32_t smem_u32(const void* p) {
    uint32_t a;
    asm("{ .reg .u64 t; cvta.to.shared.u64 t, %1; cvt.u32.u64 %0, t; }"
        : "=r"(a) : "l"(p));
    return a;
}

__device__ __forceinline__ float tf32rf(float x) {
    unsigned u;
    asm("cvt.rna.tf32.f32 %0, %1;" : "=r"(u) : "f"(x));
    return __uint_as_float(u);
}

__device__ __forceinline__ void mma_tf32(float c[4],
                                         uint32_t a0, uint32_t a1, uint32_t a2, uint32_t a3,
                                         uint32_t b0, uint32_t b1) {
    asm volatile(
        "mma.sync.aligned.m16n8k8.row.col.f32.tf32.tf32.f32 "
        "{%0,%1,%2,%3}, {%4,%5,%6,%7}, {%8,%9}, {%0,%1,%2,%3};"
        : "+f"(c[0]), "+f"(c[1]), "+f"(c[2]), "+f"(c[3])
        : "r"(a0), "r"(a1), "r"(a2), "r"(a3), "r"(b0), "r"(b1));
}

__device__ __forceinline__ void ldsm_x4(uint32_t r[4], uint32_t addr) {
    asm volatile("ldmatrix.sync.aligned.m8n8.x4.shared.b16 {%0,%1,%2,%3}, [%4];"
        : "=r"(r[0]), "=r"(r[1]), "=r"(r[2]), "=r"(r[3]) : "r"(addr));
}

__device__ __forceinline__ void cp16(uint32_t saddr, const void* gaddr) {
    asm volatile("cp.async.cg.shared.global [%0], [%1], 16;"
        :: "r"(saddr), "l"(gaddr) : "memory");
}

// ---------------------------------------------------------------------------
// Transpose + scale + tf32 round: out[n][x][d] = tf32(in[n][d][x] * mul)
// ---------------------------------------------------------------------------
__global__ __launch_bounds__(256) void transpose_scale(
    const float* __restrict__ in, float* __restrict__ out,
    int Drows, int Xcols, float mul)
{
    __shared__ float t[32][33];
    const int n  = blockIdx.z;
    const float* ib = in  + (size_t)n * Drows * Xcols;
    float*       ob = out + (size_t)n * Drows * Xcols;
    const int x0 = blockIdx.x * 32;
    const int d0 = blockIdx.y * 32;
    const int tx = threadIdx.x, ty = threadIdx.y;

    #pragma unroll
    for (int i = 0; i < 32; i += 8)
        t[ty + i][tx] = tf32rf(ib[(size_t)(d0 + ty + i) * Xcols + x0 + tx] * mul);
    __syncthreads();
    #pragma unroll
    for (int i = 0; i < 32; i += 8)
        ob[(size_t)(x0 + ty + i) * Drows + d0 + tx] = t[tx][ty + i];
}

// ---------------------------------------------------------------------------
// Elementwise tf32 rounding pass (for V)
// ---------------------------------------------------------------------------
__global__ __launch_bounds__(256) void round_tf32_kernel(
    const float4* __restrict__ in, float4* __restrict__ out)
{
    const int i = blockIdx.x * 256 + threadIdx.x;
    float4 v = in[i];
    out[i] = make_float4(tf32rf(v.x), tf32rf(v.y), tf32rf(v.z), tf32rf(v.w));
}

// ---------------------------------------------------------------------------
// tf32 tensor-core GEMM: D[m][n] = sum_k A[m][k] * B[n][k], both K-major,
// inputs pre-rounded to tf32 (HW truncation then exact).
// CTA tile 128x128, 256 threads (8 warps 2x4, warp tile 64x32).
// K chunk = 32 floats (128B row). 3-stage cp.async pipeline, ldmatrix frags.
// smem row pitch 144B -> conflict-free LDSM.
// ---------------------------------------------------------------------------
#define KC      32
#define ROWB    144                      // 36 floats pitch
#define OPBYTES (128 * ROWB)             // 18432 per operand tile
#define STGB    (2 * OPBYTES)            // 36864 per stage
#define NSTAGE  3
#define GSMEM_BYTES (NSTAGE * STGB)      // 110592

template<int NC>
__global__ __launch_bounds__(256, 2) void gemm_tc(
    const float* __restrict__ A, const float* __restrict__ B,
    float* __restrict__ D, int ldA, int ldB, int ldD,
    size_t sA, size_t sB, size_t sD)
{
    extern __shared__ char smem[];
    const uint32_t sbase = smem_u32(smem);

    const int tid  = threadIdx.x;
    const int wid  = tid >> 5;
    const int lane = tid & 31;

    const int n_b = blockIdx.z;
    const float* Ab = A + (size_t)n_b * sA;
    const float* Bb = B + (size_t)n_b * sB;
    float*       Db = D + (size_t)n_b * sD;
    const int m0 = blockIdx.y * 128;
    const int n0 = blockIdx.x * 128;

    // ---- loader mapping: 2 threads per row, 4x 16B chunks each ----
    const int lr = tid >> 1;           // row 0..127
    const int lh = tid & 1;            // half 0/1 (64B)
    const float* ag = Ab + (size_t)(m0 + lr) * ldA + lh * 16;
    const float* bg = Bb + (size_t)(n0 + lr) * ldB + lh * 16;
    const uint32_t sRow = (uint32_t)(lr * ROWB + lh * 64);

    // ---- ldmatrix per-thread offsets ----
    const int sel = lane >> 3;
    const int l7  = lane & 7;
    const int mOff = (wid >> 2) * 64;
    const int nOff = (wid & 3) * 32;

    uint32_t aOff[4], bOff[2];
    #pragma unroll
    for (int i = 0; i < 4; i++)
        aOff[i] = (uint32_t)((mOff + 16 * i + l7 + ((sel & 1) << 3)) * ROWB
                             + (((sel >> 1) << 2) << 2));
    #pragma unroll
    for (int p = 0; p < 2; p++)
        bOff[p] = (uint32_t)((nOff + 16 * p + ((sel >> 1) << 3) + l7) * ROWB
                             + (((sel & 1) << 2) << 2));

    float acc[4][4][4];
    #pragma unroll
    for (int i = 0; i < 4; i++)
        #pragma unroll
        for (int j = 0; j < 4; j++)
            #pragma unroll
            for (int r = 0; r < 4; r++) acc[i][j][r] = 0.f;

    // ---- prologue: issue stages 0..NSTAGE-1 ----
    #pragma unroll
    for (int s = 0; s < NSTAGE; s++) {
        const uint32_t as = sbase + s * STGB + sRow;
        const uint32_t bs = as + OPBYTES;
        const float* ap = ag + s * KC;
        const float* bp = bg + s * KC;
        #pragma unroll
        for (int j = 0; j < 4; j++) {
            cp16(as + j * 16, ap + j * 4);
            cp16(bs + j * 16, bp + j * 4);
        }
        asm volatile("cp.async.commit_group;" ::: "memory");
    }

    for (int c = 0; c < NC; c++) {
        asm volatile("cp.async.wait_group %0;" :: "n"(NSTAGE - 1) : "memory");
        __syncthreads();

        const uint32_t As = sbase + (c % NSTAGE) * STGB;
        const uint32_t Bs = As + OPBYTES;

        #pragma unroll
        for (int ks = 0; ks < KC / 8; ks++) {
            const uint32_t kb = ks * 32;   // 8 floats = 32 bytes
            uint32_t a[4][4], b0[4], b1[4];
            #pragma unroll
            for (int i = 0; i < 4; i++) ldsm_x4(a[i], As + aOff[i] + kb);
            ldsm_x4(b0, Bs + bOff[0] + kb);
            ldsm_x4(b1, Bs + bOff[1] + kb);

            #pragma unroll
            for (int i = 0; i < 4; i++) {
                mma_tf32(acc[i][0], a[i][0], a[i][1], a[i][2], a[i][3], b0[0], b0[1]);
                mma_tf32(acc[i][1], a[i][0], a[i][1], a[i][2], a[i][3], b0[2], b0[3]);
                mma_tf32(acc[i][2], a[i][0], a[i][1], a[i][2], a[i][3], b1[0], b1[1]);
                mma_tf32(acc[i][3], a[i][0], a[i][1], a[i][2], a[i][3], b1[2], b1[3]);
            }
        }
        __syncthreads();

        const int s = c + NSTAGE;
        if (s < NC) {
            const uint32_t as = sbase + (s % NSTAGE) * STGB + sRow;
            const uint32_t bs = as + OPBYTES;
            const float* ap = ag + s * KC;
            const float* bp = bg + s * KC;
            #pragma unroll
            for (int j = 0; j < 4; j++) {
                cp16(as + j * 16, ap + j * 4);
                cp16(bs + j * 16, bp + j * 4);
            }
        }
        asm volatile("cp.async.commit_group;" ::: "memory");
    }

    // ---- epilogue ----
    const int g   = lane >> 2;
    const int tig = lane & 3;
    #pragma unroll
    for (int i = 0; i < 4; i++) {
        const int row0 = m0 + mOff + 16 * i + g;
        #pragma unroll
        for (int j = 0; j < 4; j++) {
            const int colb = n0 + nOff + 8 * j + 2 * tig;
            *(float2*)(Db + (size_t)row0 * ldD + colb) =
                make_float2(acc[i][j][0], acc[i][j][1]);
            *(float2*)(Db + (size_t)(row0 + 8) * ldD + colb) =
                make_float2(acc[i][j][2], acc[i][j][3]);
        }
    }
}

// ---------------------------------------------------------------------------
// Fused mask + softmax over t (in place), output tf32-rounded weights.
// Mask: (t % 128) < vw[n], vw = min(128, floor(128*ratio + 0.5)).
// ---------------------------------------------------------------------------
__global__ __launch_bounds__(256) void softmax_mask_kernel(
    float* __restrict__ L, const float* __restrict__ ratios)
{
    const int row = blockIdx.x;
    const int n   = row >> 9;
    float* p = L + (size_t)row * TT;

    const float ratio = ratios[n];
    int vw = (int)floorf((float)WW * ratio + 0.5f);
    vw = vw > WW ? WW : vw;

    const int tid  = threadIdx.x;
    const int base = tid << 2;
    float4 v = ((const float4*)p)[tid];
    float vals[4] = {v.x, v.y, v.z, v.w};
    #pragma unroll
    for (int i = 0; i < 4; i++) {
        int wi = (base + i) & (WW - 1);
        if (wi >= vw) vals[i] = -INFINITY;
    }

    __shared__ float red_max[8];
    __shared__ float red_sum[8];
    const int lane = tid & 31;
    const int warp = tid >> 5;

    float m = fmaxf(fmaxf(vals[0], vals[1]), fmaxf(vals[2], vals[3]));
    #pragma unroll
    for (int off = 16; off > 0; off >>= 1)
        m = fmaxf(m, __shfl_xor_sync(0xffffffffu, m, off));
    if (lane == 0) red_max[warp] = m;
    __syncthreads();
    float mall = red_max[0];
    #pragma unroll
    for (int i = 1; i < 8; i++) mall = fmaxf(mall, red_max[i]);

    float s = 0.f;
    #pragma unroll
    for (int i = 0; i < 4; i++) {
        vals[i] = expf(vals[i] - mall);
        s += vals[i];
    }
    #pragma unroll
    for (int off = 16; off > 0; off >>= 1)
        s += __shfl_xor_sync(0xffffffffu, s, off);
    if (lane == 0) red_sum[warp] = s;
    __syncthreads();
    float sall = 0.f;
    #pragma unroll
    for (int i = 0; i < 8; i++) sall += red_sum[i];

    const float inv = 1.0f / sall;
    ((float4*)p)[tid] = make_float4(tf32rf(vals[0] * inv), tf32rf(vals[1] * inv),
                                    tf32rf(vals[2] * inv), tf32rf(vals[3] * inv));
}

// ---------------------------------------------------------------------------
extern "C" void kernel_launch(void* const* d_in, const int* in_sizes, int n_in,
                              void* d_out, int out_size)
{
    const float* query  = (const float*)d_in[0];  // [64, 512, 512]
    const float* key    = (const float*)d_in[1];  // [64, 512, 1024]
    const float* value  = (const float*)d_in[2];  // [64, 512, 1024]
    const float* ratios = (const float*)d_in[3];  // [64]
    float* out = (float*)d_out;                   // [64, 512, 512]

    float *logits = nullptr, *qt = nullptr, *kt = nullptr;
    cudaGetSymbolAddress((void**)&logits, g_logits);
    cudaGetSymbolAddress((void**)&qt, g_qt);
    cudaGetSymbolAddress((void**)&kt, g_kt);

    cudaFuncSetAttribute(gemm_tc<16>, cudaFuncAttributeMaxDynamicSharedMemorySize, GSMEM_BYTES);
    cudaFuncSetAttribute(gemm_tc<32>, cudaFuncAttributeMaxDynamicSharedMemorySize, GSMEM_BYTES);

    // 1) QT[n][c][d] = tf32(Q[n][d][c] * SCALE);  KT[n][t][d] = tf32(K[n][d][t])
    {
        dim3 blk(32, 8);
        transpose_scale<<<dim3(CQ / 32, DIM / 32, N_BATCH), blk>>>(query, qt, DIM, CQ, SCALE);
        transpose_scale<<<dim3(TT / 32, DIM / 32, N_BATCH), blk>>>(key, kt, DIM, TT, 1.0f);
    }
    // 2) logits[c][t] = QT(m=c,k=d) x KT(n=t,k=d), K=512
    {
        dim3 grid(TT / 128, CQ / 128, N_BATCH);  // (8, 4, 64)
        gemm_tc<16><<<grid, 256, GSMEM_BYTES>>>(
            qt, kt, logits, DIM, DIM, TT,
            (size_t)CQ * DIM, (size_t)TT * DIM, (size_t)CQ * TT);
    }
    // 3) V_tf32 -> reuse g_kt (stream order: runs after GEMM1 finished reading KT)
    {
        const int n4 = N_BATCH * DIM * TT / 4;   // 8388608 float4
        round_tf32_kernel<<<n4 / 256, 256>>>((const float4*)value, (float4*)kt);
    }
    // 4) mask + softmax (in place, tf32-rounded output)
    softmax_mask_kernel<<<N_BATCH * CQ, 256>>>(logits, ratios);
    // 5) out[d][c] = V(m=d,k=t) x W(n=c,k=t), K=1024
    {
        dim3 grid(CQ / 128, DIM / 128, N_BATCH);  // (4, 4, 64)
        gemm_tc<32><<<grid, 256, GSMEM_BYTES>>>(
            kt, logits, out, TT, TT, CQ,
            (size_t)DIM * TT, (size_t)CQ * TT, (size_t)DIM * CQ);
    }
}